// round 2
// baseline (speedup 1.0000x reference)
#include <cuda_runtime.h>
#include <math.h>

#define SEQ     4096
#define HID     2048
#define NHEADS  16
#define HDIM    128
#define NGLOB   16
#define HALFWIN 256
#define SCALE   0.08838834764831845f   // 128^-0.5

// -------- scratch (static device arrays; no allocation allowed) --------
__device__ float g_Q[SEQ * HID];
__device__ float g_K[SEQ * HID];
__device__ float g_V[SEQ * HID];
__device__ float g_O[SEQ * HID];

// ======================= SGEMM (fp32 SIMT) =======================
// C[M,N] = alpha * A[M,K] @ B[K,N], all row-major. BM=BN=128, BK=16,
// 256 threads, 8x8 per thread.
#define BM 128
#define BN 128
#define BK 16

__global__ __launch_bounds__(256) void sgemm_kernel(
    const float* __restrict__ A, const float* __restrict__ B,
    float* __restrict__ C, int M, int N, int K, float alpha)
{
    __shared__ float As[BK][BM];   // transposed: As[k][m]
    __shared__ float Bs[BK][BN];

    const int tid = threadIdx.x;
    const int tx = tid & 15;        // 16 col-threads
    const int ty = tid >> 4;        // 16 row-threads
    const int row0 = blockIdx.y * BM;
    const int col0 = blockIdx.x * BN;

    const int aRow  = tid >> 2;         // 4 float4 per 16-wide A row
    const int aCol4 = (tid & 3) * 4;
    const int bRow  = tid >> 5;         // 32 float4 per 128-wide B row
    const int bCol4 = (tid & 31) * 4;

    float acc[8][8];
#pragma unroll
    for (int i = 0; i < 8; i++)
#pragma unroll
        for (int j = 0; j < 8; j++) acc[i][j] = 0.f;

    for (int kt = 0; kt < K; kt += BK) {
        // load A tile (128x16) transposed into As[k][m]
#pragma unroll
        for (int s = 0; s < 2; s++) {
            int r = aRow + s * 64;
            float4 v = *(const float4*)&A[(size_t)(row0 + r) * K + kt + aCol4];
            As[aCol4 + 0][r] = v.x;
            As[aCol4 + 1][r] = v.y;
            As[aCol4 + 2][r] = v.z;
            As[aCol4 + 3][r] = v.w;
        }
        // load B tile (16x128)
#pragma unroll
        for (int s = 0; s < 2; s++) {
            int r = bRow + s * 8;
            *(float4*)&Bs[r][bCol4] =
                *(const float4*)&B[(size_t)(kt + r) * N + col0 + bCol4];
        }
        __syncthreads();

#pragma unroll
        for (int k = 0; k < BK; k++) {
            float a[8], b[8];
            *(float4*)&a[0] = *(const float4*)&As[k][ty * 8];
            *(float4*)&a[4] = *(const float4*)&As[k][ty * 8 + 4];
            *(float4*)&b[0] = *(const float4*)&Bs[k][tx * 8];
            *(float4*)&b[4] = *(const float4*)&Bs[k][tx * 8 + 4];
#pragma unroll
            for (int i = 0; i < 8; i++)
#pragma unroll
                for (int j = 0; j < 8; j++)
                    acc[i][j] = fmaf(a[i], b[j], acc[i][j]);
        }
        __syncthreads();
    }

#pragma unroll
    for (int i = 0; i < 8; i++) {
        int row = row0 + ty * 8 + i;
#pragma unroll
        for (int j4 = 0; j4 < 2; j4++) {
            float4 o;
            o.x = alpha * acc[i][j4 * 4 + 0];
            o.y = alpha * acc[i][j4 * 4 + 1];
            o.z = alpha * acc[i][j4 * 4 + 2];
            o.w = alpha * acc[i][j4 * 4 + 3];
            *(float4*)&C[(size_t)row * N + col0 + tx * 8 + j4 * 4] = o;
        }
    }
}

// ======================= Attention (flash-style fp32) =======================
// grid (SEQ/64, NHEADS), 256 threads. Q tile 64, K tile 64, head dim 128.
// Q is pre-scaled by SCALE. Sparsity: include key tiles only where the
// sliding window / global mask can be nonzero; elementwise mask inside tile.
//
// smem (dynamic, floats):
//   Qs[128][68]  (transposed, Qs[d][q])        8704
//   Ks[128][68]  (transposed, Ks[d][k])        8704
//   Vs[64][132]  (Vs[k][d])                    8448
//   Ps[64][68]   (Ps[q][k])                    4352
#define QS_OFF  0
#define KS_OFF  8704
#define VS_OFF  17408
#define PS_OFF  25856
#define ATTN_SMEM_FLOATS 30208
#define ATTN_SMEM_BYTES  (ATTN_SMEM_FLOATS * 4)

__global__ __launch_bounds__(256) void attn_kernel(
    const float* __restrict__ Q, const float* __restrict__ K,
    const float* __restrict__ V, float* __restrict__ O)
{
    extern __shared__ float sm[];
    float* Qs = sm + QS_OFF;
    float* Ks = sm + KS_OFF;
    float* Vs = sm + VS_OFF;
    float* Ps = sm + PS_OFF;

    const int tid = threadIdx.x;
    const int tx = tid & 15;
    const int ty = tid >> 4;
    const int q0 = blockIdx.x * 64;
    const int h  = blockIdx.y;
    const size_t hoff = (size_t)h * HDIM;

    // load Q tile transposed
    for (int f = tid; f < 64 * 32; f += 256) {
        int r  = f >> 5;
        int d4 = (f & 31) * 4;
        float4 v = *(const float4*)&Q[(size_t)(q0 + r) * HID + hoff + d4];
        Qs[(d4 + 0) * 68 + r] = v.x;
        Qs[(d4 + 1) * 68 + r] = v.y;
        Qs[(d4 + 2) * 68 + r] = v.z;
        Qs[(d4 + 3) * 68 + r] = v.w;
    }

    float acc[4][8];
#pragma unroll
    for (int i = 0; i < 4; i++)
#pragma unroll
        for (int j = 0; j < 8; j++) acc[i][j] = 0.f;
    float mrow[4], lrow[4];
#pragma unroll
    for (int i = 0; i < 4; i++) { mrow[i] = -1e30f; lrow[i] = 0.f; }

    __syncthreads();

    for (int t = 0; t < SEQ / 64; t++) {
        const int k0 = t * 64;
        bool include = (q0 == 0) || (t == 0) ||
                       ((k0 + 63 >= q0 - (HALFWIN - 1)) && (k0 <= q0 + 63 + (HALFWIN - 1)));
        if (!include) continue;

        // load K (transposed) and V tiles
        for (int f = tid; f < 64 * 32; f += 256) {
            int r  = f >> 5;
            int d4 = (f & 31) * 4;
            float4 kv = *(const float4*)&K[(size_t)(k0 + r) * HID + hoff + d4];
            Ks[(d4 + 0) * 68 + r] = kv.x;
            Ks[(d4 + 1) * 68 + r] = kv.y;
            Ks[(d4 + 2) * 68 + r] = kv.z;
            Ks[(d4 + 3) * 68 + r] = kv.w;
            float4 vv = *(const float4*)&V[(size_t)(k0 + r) * HID + hoff + d4];
            *(float4*)&Vs[r * 132 + d4] = vv;
        }
        __syncthreads();

        // S tile: 4x4 per thread
        float s[4][4];
#pragma unroll
        for (int i = 0; i < 4; i++)
#pragma unroll
            for (int j = 0; j < 4; j++) s[i][j] = 0.f;

#pragma unroll 4
        for (int d = 0; d < HDIM; d++) {
            float4 a = *(const float4*)&Qs[d * 68 + ty * 4];
            float4 b = *(const float4*)&Ks[d * 68 + tx * 4];
            float av[4] = {a.x, a.y, a.z, a.w};
            float bv[4] = {b.x, b.y, b.z, b.w};
#pragma unroll
            for (int i = 0; i < 4; i++)
#pragma unroll
                for (int j = 0; j < 4; j++)
                    s[i][j] = fmaf(av[i], bv[j], s[i][j]);
        }

        // mask + online softmax (row state replicated across the 16 tx lanes)
#pragma unroll
        for (int i = 0; i < 4; i++) {
            const int qg = q0 + ty * 4 + i;
#pragma unroll
            for (int j = 0; j < 4; j++) {
                const int kg = k0 + tx * 4 + j;
                bool allowed = (qg < NGLOB) || (kg < NGLOB) ||
                               (abs(qg - kg) < HALFWIN);
                if (!allowed) s[i][j] = -1e30f;
            }
            float rm = fmaxf(fmaxf(s[i][0], s[i][1]), fmaxf(s[i][2], s[i][3]));
            rm = fmaxf(rm, __shfl_xor_sync(0xffffffffu, rm, 1));
            rm = fmaxf(rm, __shfl_xor_sync(0xffffffffu, rm, 2));
            rm = fmaxf(rm, __shfl_xor_sync(0xffffffffu, rm, 4));
            rm = fmaxf(rm, __shfl_xor_sync(0xffffffffu, rm, 8));

            float mn  = fmaxf(mrow[i], rm);
            float fac = __expf(mrow[i] - mn);
            float rs = 0.f;
#pragma unroll
            for (int j = 0; j < 4; j++) {
                float pv = __expf(s[i][j] - mn);
                s[i][j] = pv;
                rs += pv;
            }
            rs += __shfl_xor_sync(0xffffffffu, rs, 1);
            rs += __shfl_xor_sync(0xffffffffu, rs, 2);
            rs += __shfl_xor_sync(0xffffffffu, rs, 4);
            rs += __shfl_xor_sync(0xffffffffu, rs, 8);

            lrow[i] = lrow[i] * fac + rs;
            mrow[i] = mn;
#pragma unroll
            for (int j = 0; j < 8; j++) acc[i][j] *= fac;

            float4 pw;
            pw.x = s[i][0]; pw.y = s[i][1]; pw.z = s[i][2]; pw.w = s[i][3];
            *(float4*)&Ps[(ty * 4 + i) * 68 + tx * 4] = pw;
        }
        // Ps rows are written & read within the same warp's lanes -> no block
        // sync needed before PV; Vs already synced after the tile load.

        // PV: acc[q][d] += P[q][k] * V[k][d]
#pragma unroll 2
        for (int k = 0; k < 64; k++) {
            float v[8];
            *(float4*)&v[0] = *(const float4*)&Vs[k * 132 + tx * 8];
            *(float4*)&v[4] = *(const float4*)&Vs[k * 132 + tx * 8 + 4];
#pragma unroll
            for (int i = 0; i < 4; i++) {
                float pv = Ps[(ty * 4 + i) * 68 + k];
#pragma unroll
                for (int j = 0; j < 8; j++)
                    acc[i][j] = fmaf(pv, v[j], acc[i][j]);
            }
        }
        __syncthreads();   // protect Ks/Vs/Ps before next tile's loads
    }

    // epilogue: normalize and store
#pragma unroll
    for (int i = 0; i < 4; i++) {
        float inv = 1.f / lrow[i];
        int row = q0 + ty * 4 + i;
#pragma unroll
        for (int j4 = 0; j4 < 2; j4++) {
            float4 o;
            o.x = acc[i][j4 * 4 + 0] * inv;
            o.y = acc[i][j4 * 4 + 1] * inv;
            o.z = acc[i][j4 * 4 + 2] * inv;
            o.w = acc[i][j4 * 4 + 3] * inv;
            *(float4*)&O[(size_t)row * HID + hoff + tx * 8 + j4 * 4] = o;
        }
    }
}

// ======================= launch =======================
extern "C" void kernel_launch(void* const* d_in, const int* in_sizes, int n_in,
                              void* d_out, int out_size)
{
    const float* X  = (const float*)d_in[0];
    const float* Wq = (const float*)d_in[1];
    const float* Wk = (const float*)d_in[2];
    const float* Wv = (const float*)d_in[3];
    const float* Wo = (const float*)d_in[4];
    float* out = (float*)d_out;

    float *qp, *kp, *vp, *op;
    cudaGetSymbolAddress((void**)&qp, g_Q);
    cudaGetSymbolAddress((void**)&kp, g_K);
    cudaGetSymbolAddress((void**)&vp, g_V);
    cudaGetSymbolAddress((void**)&op, g_O);

    cudaFuncSetAttribute(attn_kernel,
                         cudaFuncAttributeMaxDynamicSharedMemorySize,
                         ATTN_SMEM_BYTES);

    dim3 gG(HID / BN, SEQ / BM);   // (16, 32)
    sgemm_kernel<<<gG, 256>>>(X, Wq, qp, SEQ, HID, HID, SCALE);
    sgemm_kernel<<<gG, 256>>>(X, Wk, kp, SEQ, HID, HID, 1.0f);
    sgemm_kernel<<<gG, 256>>>(X, Wv, vp, SEQ, HID, HID, 1.0f);

    attn_kernel<<<dim3(SEQ / 64, NHEADS), 256, ATTN_SMEM_BYTES>>>(qp, kp, vp, op);

    sgemm_kernel<<<gG, 256>>>(op, Wo, out, SEQ, HID, HID, 1.0f);
}

// round 6
// speedup vs baseline: 1.5609x; 1.5609x over previous
#include <cuda_runtime.h>
#include <cuda_bf16.h>
#include <cstdint>
#include <math.h>

#define SEQ     4096
#define HID     2048
#define NHEADS  16
#define HDIM    128
#define NGLOB   16
#define HALFWIN 256
#define SCALE   0.08838834764831845f   // 128^-0.5

// ---------------- scratch (static device arrays) ----------------
__device__ float g_Q[SEQ * HID];
__device__ float g_K[SEQ * HID];
__device__ float g_V[SEQ * HID];
__device__ float g_O[SEQ * HID];
__device__ __nv_bfloat16 g_Xh[SEQ * HID], g_Xl[SEQ * HID];
__device__ __nv_bfloat16 g_Oh[SEQ * HID], g_Ol[SEQ * HID];
__device__ __nv_bfloat16 g_Wqh[HID * HID], g_Wql[HID * HID];
__device__ __nv_bfloat16 g_Wkh[HID * HID], g_Wkl[HID * HID];
__device__ __nv_bfloat16 g_Wvh[HID * HID], g_Wvl[HID * HID];
__device__ __nv_bfloat16 g_Woh[HID * HID], g_Wol[HID * HID];

// ---------------- mma.sync helpers (compute_103-legal) ----------------
__device__ __forceinline__ uint32_t smem_u32(const void* p) {
    uint32_t a;
    asm("{ .reg .u64 t; cvta.to.shared.u64 t, %1; cvt.u32.u64 %0, t; }" : "=r"(a) : "l"(p));
    return a;
}
__device__ __forceinline__ void ldsm_x4(uint32_t& r0, uint32_t& r1, uint32_t& r2,
                                        uint32_t& r3, uint32_t addr) {
    asm volatile("ldmatrix.sync.aligned.m8n8.x4.shared.b16 {%0,%1,%2,%3}, [%4];"
                 : "=r"(r0), "=r"(r1), "=r"(r2), "=r"(r3) : "r"(addr));
}
__device__ __forceinline__ void ldsm_x2(uint32_t& r0, uint32_t& r1, uint32_t addr) {
    asm volatile("ldmatrix.sync.aligned.m8n8.x2.shared.b16 {%0,%1}, [%2];"
                 : "=r"(r0), "=r"(r1) : "r"(addr));
}
__device__ __forceinline__ void mma_bf16(float* c, const uint32_t* a, const uint32_t* b) {
    asm volatile(
        "mma.sync.aligned.m16n8k16.row.col.f32.bf16.bf16.f32 "
        "{%0,%1,%2,%3}, {%4,%5,%6,%7}, {%8,%9}, {%0,%1,%2,%3};"
        : "+f"(c[0]), "+f"(c[1]), "+f"(c[2]), "+f"(c[3])
        : "r"(a[0]), "r"(a[1]), "r"(a[2]), "r"(a[3]), "r"(b[0]), "r"(b[1]));
}

// ---------------- conversion kernels ----------------
__global__ __launch_bounds__(256) void split_kernel(
    const float* __restrict__ x, __nv_bfloat16* __restrict__ h,
    __nv_bfloat16* __restrict__ l, int n4)
{
    int i = blockIdx.x * blockDim.x + threadIdx.x;
    if (i >= n4) return;
    float4 v = ((const float4*)x)[i];
    __nv_bfloat16 h0 = __float2bfloat16(v.x);
    __nv_bfloat16 h1 = __float2bfloat16(v.y);
    __nv_bfloat16 h2 = __float2bfloat16(v.z);
    __nv_bfloat16 h3 = __float2bfloat16(v.w);
    __nv_bfloat16 l0 = __float2bfloat16(v.x - __bfloat162float(h0));
    __nv_bfloat16 l1 = __float2bfloat16(v.y - __bfloat162float(h1));
    __nv_bfloat16 l2 = __float2bfloat16(v.z - __bfloat162float(h2));
    __nv_bfloat16 l3 = __float2bfloat16(v.w - __bfloat162float(h3));
    ((__nv_bfloat162*)h)[2 * i]     = __halves2bfloat162(h0, h1);
    ((__nv_bfloat162*)h)[2 * i + 1] = __halves2bfloat162(h2, h3);
    ((__nv_bfloat162*)l)[2 * i]     = __halves2bfloat162(l0, l1);
    ((__nv_bfloat162*)l)[2 * i + 1] = __halves2bfloat162(l2, l3);
}

// W[K][N] (row-major) -> Th[N][K], Tl[N][K] split bf16
__global__ __launch_bounds__(256) void tsplit_kernel(
    const float* __restrict__ W, __nv_bfloat16* __restrict__ Th,
    __nv_bfloat16* __restrict__ Tl)
{
    __shared__ float t[32][33];
    int tx = threadIdx.x, ty = threadIdx.y;
    int bx = blockIdx.x * 32;   // N
    int by = blockIdx.y * 32;   // K
#pragma unroll
    for (int j = 0; j < 32; j += 8)
        t[ty + j][tx] = W[(size_t)(by + ty + j) * HID + bx + tx];
    __syncthreads();
#pragma unroll
    for (int j = 0; j < 32; j += 8) {
        float v = t[tx][ty + j];
        __nv_bfloat16 hb = __float2bfloat16(v);
        float lo = v - __bfloat162float(hb);
        size_t o = (size_t)(bx + ty + j) * HID + by + tx;
        Th[o] = hb;
        Tl[o] = __float2bfloat16(lo);
    }
}

// ---------------- HMMA bf16-split GEMM ----------------
// C[M,N] = alpha * (Ah+Al)[M,K] @ (Bh+Bl)^T   (Bt stored [N][K] K-major)
// CTA 128x128, BK=32, 8 warps in 2x4, warp tile 64x32.
// smem rows padded to 40 bf16 (80B) -> conflict-free ldmatrix.
#define BK 32
#define SSTRIDE 40                     // elems per row
#define TILE_ELEMS (128 * SSTRIDE)     // 5120 elems per buffer

__global__ __launch_bounds__(256) void gemm_mma(
    const __nv_bfloat16* __restrict__ Ah, const __nv_bfloat16* __restrict__ Al,
    const __nv_bfloat16* __restrict__ Bth, const __nv_bfloat16* __restrict__ Btl,
    float* __restrict__ C, int M, int N, int K, float alpha)
{
    __shared__ __align__(16) __nv_bfloat16 sm[4 * TILE_ELEMS];  // Ah, Al, Bh, Bl
    __nv_bfloat16* sAh = sm;
    __nv_bfloat16* sAl = sm + TILE_ELEMS;
    __nv_bfloat16* sBh = sm + 2 * TILE_ELEMS;
    __nv_bfloat16* sBl = sm + 3 * TILE_ELEMS;

    const int tid = threadIdx.x;
    const int wid = tid >> 5;
    const int lid = tid & 31;
    const int row0 = blockIdx.y * 128;
    const int col0 = blockIdx.x * 128;

    // ---- global load mapping: 2 threads per row, 32B (16 elems) each ----
    const int lrow = tid >> 1;
    const int lhalf = (tid & 1) * 16;          // elem offset within BK row
    const __nv_bfloat16* aph = Ah  + (size_t)(row0 + lrow) * K + lhalf;
    const __nv_bfloat16* apl = Al  + (size_t)(row0 + lrow) * K + lhalf;
    const __nv_bfloat16* bph = Bth + (size_t)(col0 + lrow) * K + lhalf;
    const __nv_bfloat16* bpl = Btl + (size_t)(col0 + lrow) * K + lhalf;
    const int soff = lrow * SSTRIDE + lhalf;   // smem elem offset

    // ---- warp tile bases ----
    const int warpM = (wid >> 2) * 64;
    const int warpN = (wid & 3) * 32;

    // ldmatrix lane addressing (elem offsets within tile)
    const int aRow = warpM + (lid & 15);            // + mt*16
    const int aCol = (lid >> 4) * 8;                // + ks*16
    const int bRow = warpN + (lid & 7);             // + nt*8
    const int bCol = ((lid >> 3) & 1) * 8;          // + ks*16

    const uint32_t sAh_u = smem_u32(sAh);
    const uint32_t sAl_u = smem_u32(sAl);
    const uint32_t sBh_u = smem_u32(sBh);
    const uint32_t sBl_u = smem_u32(sBl);

    float acc[4][4][4];
#pragma unroll
    for (int i = 0; i < 4; i++)
#pragma unroll
        for (int j = 0; j < 4; j++)
#pragma unroll
            for (int k = 0; k < 4; k++) acc[i][j][k] = 0.f;

    // preload chunk 0 into regs
    uint4 ra[2], rl[2], rb[2], rm[2];
#pragma unroll
    for (int i = 0; i < 2; i++) {
        ra[i] = *(const uint4*)(aph + i * 8);
        rl[i] = *(const uint4*)(apl + i * 8);
        rb[i] = *(const uint4*)(bph + i * 8);
        rm[i] = *(const uint4*)(bpl + i * 8);
    }

    const int nch = K / BK;
    for (int c = 0; c < nch; c++) {
        __syncthreads();   // previous chunk's consumers done
#pragma unroll
        for (int i = 0; i < 2; i++) {
            *(uint4*)(sAh + soff + i * 8) = ra[i];
            *(uint4*)(sAl + soff + i * 8) = rl[i];
            *(uint4*)(sBh + soff + i * 8) = rb[i];
            *(uint4*)(sBl + soff + i * 8) = rm[i];
        }
        __syncthreads();

        if (c + 1 < nch) {
            const int off = (c + 1) * BK;
#pragma unroll
            for (int i = 0; i < 2; i++) {
                ra[i] = *(const uint4*)(aph + off + i * 8);
                rl[i] = *(const uint4*)(apl + off + i * 8);
                rb[i] = *(const uint4*)(bph + off + i * 8);
                rm[i] = *(const uint4*)(bpl + off + i * 8);
            }
        }

#pragma unroll
        for (int ks = 0; ks < 2; ks++) {
            // B fragments: 4 ntiles, hi+lo
            uint32_t bh[4][2], bl[4][2];
            const uint32_t bOff = (uint32_t)((bRow)*SSTRIDE + ks * 16 + bCol) * 2;
#pragma unroll
            for (int nt = 0; nt < 4; nt++) {
                ldsm_x2(bh[nt][0], bh[nt][1], sBh_u + bOff + nt * 8 * SSTRIDE * 2);
                ldsm_x2(bl[nt][0], bl[nt][1], sBl_u + bOff + nt * 8 * SSTRIDE * 2);
            }
            const uint32_t aOff = (uint32_t)((aRow)*SSTRIDE + ks * 16 + aCol) * 2;
#pragma unroll
            for (int mt = 0; mt < 4; mt++) {
                uint32_t ah[4], al[4];
                ldsm_x4(ah[0], ah[1], ah[2], ah[3], sAh_u + aOff + mt * 16 * SSTRIDE * 2);
                ldsm_x4(al[0], al[1], al[2], al[3], sAl_u + aOff + mt * 16 * SSTRIDE * 2);
#pragma unroll
                for (int nt = 0; nt < 4; nt++) {
                    mma_bf16(acc[mt][nt], ah, bh[nt]);
                    mma_bf16(acc[mt][nt], ah, bl[nt]);
                    mma_bf16(acc[mt][nt], al, bh[nt]);
                }
            }
        }
    }

    // ---- epilogue: fragment -> gmem ----
    const int qrow = lid >> 2;          // 0..7
    const int qcol = (lid & 3) * 2;     // 0,2,4,6
#pragma unroll
    for (int mt = 0; mt < 4; mt++) {
        const int r0g = row0 + warpM + mt * 16 + qrow;
#pragma unroll
        for (int nt = 0; nt < 4; nt++) {
            const int cg = col0 + warpN + nt * 8 + qcol;
            float2 v0, v1;
            v0.x = alpha * acc[mt][nt][0];
            v0.y = alpha * acc[mt][nt][1];
            v1.x = alpha * acc[mt][nt][2];
            v1.y = alpha * acc[mt][nt][3];
            *(float2*)&C[(size_t)r0g * N + cg]       = v0;
            *(float2*)&C[(size_t)(r0g + 8) * N + cg] = v1;
        }
    }
}

// ======================= Attention (flash-style fp32, unchanged) =======================
#define QS_OFF  0
#define KS_OFF  8704
#define VS_OFF  17408
#define PS_OFF  25856
#define ATTN_SMEM_FLOATS 30208
#define ATTN_SMEM_BYTES  (ATTN_SMEM_FLOATS * 4)

__global__ __launch_bounds__(256) void attn_kernel(
    const float* __restrict__ Q, const float* __restrict__ K,
    const float* __restrict__ V, float* __restrict__ O)
{
    extern __shared__ float smf[];
    float* Qs = smf + QS_OFF;
    float* Ks = smf + KS_OFF;
    float* Vs = smf + VS_OFF;
    float* Ps = smf + PS_OFF;

    const int tid = threadIdx.x;
    const int tx = tid & 15;
    const int ty = tid >> 4;
    const int q0 = blockIdx.x * 64;
    const int h  = blockIdx.y;
    const size_t hoff = (size_t)h * HDIM;

    for (int f = tid; f < 64 * 32; f += 256) {
        int r  = f >> 5;
        int d4 = (f & 31) * 4;
        float4 v = *(const float4*)&Q[(size_t)(q0 + r) * HID + hoff + d4];
        Qs[(d4 + 0) * 68 + r] = v.x;
        Qs[(d4 + 1) * 68 + r] = v.y;
        Qs[(d4 + 2) * 68 + r] = v.z;
        Qs[(d4 + 3) * 68 + r] = v.w;
    }

    float acc[4][8];
#pragma unroll
    for (int i = 0; i < 4; i++)
#pragma unroll
        for (int j = 0; j < 8; j++) acc[i][j] = 0.f;
    float mrow[4], lrow[4];
#pragma unroll
    for (int i = 0; i < 4; i++) { mrow[i] = -1e30f; lrow[i] = 0.f; }

    __syncthreads();

    for (int t = 0; t < SEQ / 64; t++) {
        const int k0 = t * 64;
        bool include = (q0 == 0) || (t == 0) ||
                       ((k0 + 63 >= q0 - (HALFWIN - 1)) && (k0 <= q0 + 63 + (HALFWIN - 1)));
        if (!include) continue;

        for (int f = tid; f < 64 * 32; f += 256) {
            int r  = f >> 5;
            int d4 = (f & 31) * 4;
            float4 kv = *(const float4*)&K[(size_t)(k0 + r) * HID + hoff + d4];
            Ks[(d4 + 0) * 68 + r] = kv.x;
            Ks[(d4 + 1) * 68 + r] = kv.y;
            Ks[(d4 + 2) * 68 + r] = kv.z;
            Ks[(d4 + 3) * 68 + r] = kv.w;
            float4 vv = *(const float4*)&V[(size_t)(k0 + r) * HID + hoff + d4];
            *(float4*)&Vs[r * 132 + d4] = vv;
        }
        __syncthreads();

        float s[4][4];
#pragma unroll
        for (int i = 0; i < 4; i++)
#pragma unroll
            for (int j = 0; j < 4; j++) s[i][j] = 0.f;

#pragma unroll 4
        for (int d = 0; d < HDIM; d++) {
            float4 a = *(const float4*)&Qs[d * 68 + ty * 4];
            float4 b = *(const float4*)&Ks[d * 68 + tx * 4];
            float av[4] = {a.x, a.y, a.z, a.w};
            float bv[4] = {b.x, b.y, b.z, b.w};
#pragma unroll
            for (int i = 0; i < 4; i++)
#pragma unroll
                for (int j = 0; j < 4; j++)
                    s[i][j] = fmaf(av[i], bv[j], s[i][j]);
        }

#pragma unroll
        for (int i = 0; i < 4; i++) {
            const int qg = q0 + ty * 4 + i;
#pragma unroll
            for (int j = 0; j < 4; j++) {
                const int kg = k0 + tx * 4 + j;
                bool allowed = (qg < NGLOB) || (kg < NGLOB) ||
                               (abs(qg - kg) < HALFWIN);
                if (!allowed) s[i][j] = -1e30f;
            }
            float rm = fmaxf(fmaxf(s[i][0], s[i][1]), fmaxf(s[i][2], s[i][3]));
            rm = fmaxf(rm, __shfl_xor_sync(0xffffffffu, rm, 1));
            rm = fmaxf(rm, __shfl_xor_sync(0xffffffffu, rm, 2));
            rm = fmaxf(rm, __shfl_xor_sync(0xffffffffu, rm, 4));
            rm = fmaxf(rm, __shfl_xor_sync(0xffffffffu, rm, 8));

            float mn  = fmaxf(mrow[i], rm);
            float fac = __expf(mrow[i] - mn);
            float rs = 0.f;
#pragma unroll
            for (int j = 0; j < 4; j++) {
                float pv = __expf(s[i][j] - mn);
                s[i][j] = pv;
                rs += pv;
            }
            rs += __shfl_xor_sync(0xffffffffu, rs, 1);
            rs += __shfl_xor_sync(0xffffffffu, rs, 2);
            rs += __shfl_xor_sync(0xffffffffu, rs, 4);
            rs += __shfl_xor_sync(0xffffffffu, rs, 8);

            lrow[i] = lrow[i] * fac + rs;
            mrow[i] = mn;
#pragma unroll
            for (int j = 0; j < 8; j++) acc[i][j] *= fac;

            float4 pw;
            pw.x = s[i][0]; pw.y = s[i][1]; pw.z = s[i][2]; pw.w = s[i][3];
            *(float4*)&Ps[(ty * 4 + i) * 68 + tx * 4] = pw;
        }

#pragma unroll 2
        for (int k = 0; k < 64; k++) {
            float v[8];
            *(float4*)&v[0] = *(const float4*)&Vs[k * 132 + tx * 8];
            *(float4*)&v[4] = *(const float4*)&Vs[k * 132 + tx * 8 + 4];
#pragma unroll
            for (int i = 0; i < 4; i++) {
                float pv = Ps[(ty * 4 + i) * 68 + k];
#pragma unroll
                for (int j = 0; j < 8; j++)
                    acc[i][j] = fmaf(pv, v[j], acc[i][j]);
            }
        }
        __syncthreads();
    }

#pragma unroll
    for (int i = 0; i < 4; i++) {
        float inv = 1.f / lrow[i];
        int row = q0 + ty * 4 + i;
#pragma unroll
        for (int j4 = 0; j4 < 2; j4++) {
            float4 o;
            o.x = acc[i][j4 * 4 + 0] * inv;
            o.y = acc[i][j4 * 4 + 1] * inv;
            o.z = acc[i][j4 * 4 + 2] * inv;
            o.w = acc[i][j4 * 4 + 3] * inv;
            *(float4*)&O[(size_t)row * HID + hoff + tx * 8 + j4 * 4] = o;
        }
    }
}

// ======================= launch =======================
extern "C" void kernel_launch(void* const* d_in, const int* in_sizes, int n_in,
                              void* d_out, int out_size)
{
    const float* X  = (const float*)d_in[0];
    const float* Wq = (const float*)d_in[1];
    const float* Wk = (const float*)d_in[2];
    const float* Wv = (const float*)d_in[3];
    const float* Wo = (const float*)d_in[4];
    float* out = (float*)d_out;

    float *qp, *kp, *vp, *op;
    cudaGetSymbolAddress((void**)&qp, g_Q);
    cudaGetSymbolAddress((void**)&kp, g_K);
    cudaGetSymbolAddress((void**)&vp, g_V);
    cudaGetSymbolAddress((void**)&op, g_O);
    __nv_bfloat16 *xh, *xl, *oh, *ol;
    cudaGetSymbolAddress((void**)&xh, g_Xh);
    cudaGetSymbolAddress((void**)&xl, g_Xl);
    cudaGetSymbolAddress((void**)&oh, g_Oh);
    cudaGetSymbolAddress((void**)&ol, g_Ol);
    __nv_bfloat16 *wqh, *wql, *wkh, *wkl, *wvh, *wvl, *woh, *wol;
    cudaGetSymbolAddress((void**)&wqh, g_Wqh);
    cudaGetSymbolAddress((void**)&wql, g_Wql);
    cudaGetSymbolAddress((void**)&wkh, g_Wkh);
    cudaGetSymbolAddress((void**)&wkl, g_Wkl);
    cudaGetSymbolAddress((void**)&wvh, g_Wvh);
    cudaGetSymbolAddress((void**)&wvl, g_Wvl);
    cudaGetSymbolAddress((void**)&woh, g_Woh);
    cudaGetSymbolAddress((void**)&wol, g_Wol);

    cudaFuncSetAttribute(attn_kernel,
                         cudaFuncAttributeMaxDynamicSharedMemorySize, ATTN_SMEM_BYTES);

    const int n4 = SEQ * HID / 4;
    split_kernel<<<(n4 + 255) / 256, 256>>>(X, xh, xl, n4);
    dim3 tG(HID / 32, HID / 32);
    dim3 tB(32, 8);
    tsplit_kernel<<<tG, tB>>>(Wq, wqh, wql);
    tsplit_kernel<<<tG, tB>>>(Wk, wkh, wkl);
    tsplit_kernel<<<tG, tB>>>(Wv, wvh, wvl);
    tsplit_kernel<<<tG, tB>>>(Wo, woh, wol);

    dim3 gG(HID / 128, SEQ / 128);   // (16, 32)
    gemm_mma<<<gG, 256>>>(xh, xl, wqh, wql, qp, SEQ, HID, HID, SCALE);
    gemm_mma<<<gG, 256>>>(xh, xl, wkh, wkl, kp, SEQ, HID, HID, 1.0f);
    gemm_mma<<<gG, 256>>>(xh, xl, wvh, wvl, vp, SEQ, HID, HID, 1.0f);

    attn_kernel<<<dim3(SEQ / 64, NHEADS), 256, ATTN_SMEM_BYTES>>>(qp, kp, vp, op);

    split_kernel<<<(n4 + 255) / 256, 256>>>(op, oh, ol, n4);
    gemm_mma<<<gG, 256>>>(oh, ol, woh, wol, out, SEQ, HID, HID, 1.0f);
}

// round 8
// speedup vs baseline: 2.5292x; 1.6203x over previous
#include <cuda_runtime.h>
#include <cuda_bf16.h>
#include <cstdint>
#include <math.h>

#define SEQ     4096
#define HID     2048
#define NHEADS  16
#define HDIM    128
#define NGLOB   16
#define HALFWIN 256
#define SCALE   0.08838834764831845f   // 128^-0.5

// ---------------- scratch (static device arrays) ----------------
__device__ __nv_bfloat16 g_Xh[SEQ * HID], g_Xl[SEQ * HID];
__device__ __nv_bfloat16 g_Qh[SEQ * HID], g_Ql[SEQ * HID];
__device__ __nv_bfloat16 g_Kh[SEQ * HID], g_Kl[SEQ * HID];
__device__ __nv_bfloat16 g_Vh[SEQ * HID], g_Vl[SEQ * HID];
__device__ __nv_bfloat16 g_Oh[SEQ * HID], g_Ol[SEQ * HID];
__device__ __nv_bfloat16 g_Wqh[HID * HID], g_Wql[HID * HID];
__device__ __nv_bfloat16 g_Wkh[HID * HID], g_Wkl[HID * HID];
__device__ __nv_bfloat16 g_Wvh[HID * HID], g_Wvl[HID * HID];
__device__ __nv_bfloat16 g_Woh[HID * HID], g_Wol[HID * HID];

// ---------------- asm helpers (compute_103-legal) ----------------
__device__ __forceinline__ uint32_t smem_u32(const void* p) {
    uint32_t a;
    asm("{ .reg .u64 t; cvta.to.shared.u64 t, %1; cvt.u32.u64 %0, t; }" : "=r"(a) : "l"(p));
    return a;
}
__device__ __forceinline__ void ldsm_x4(uint32_t& r0, uint32_t& r1, uint32_t& r2,
                                        uint32_t& r3, uint32_t addr) {
    asm volatile("ldmatrix.sync.aligned.m8n8.x4.shared.b16 {%0,%1,%2,%3}, [%4];"
                 : "=r"(r0), "=r"(r1), "=r"(r2), "=r"(r3) : "r"(addr));
}
__device__ __forceinline__ void ldsm_x2(uint32_t& r0, uint32_t& r1, uint32_t addr) {
    asm volatile("ldmatrix.sync.aligned.m8n8.x2.shared.b16 {%0,%1}, [%2];"
                 : "=r"(r0), "=r"(r1) : "r"(addr));
}
__device__ __forceinline__ void ldsm_x2t(uint32_t& r0, uint32_t& r1, uint32_t addr) {
    asm volatile("ldmatrix.sync.aligned.m8n8.x2.trans.shared.b16 {%0,%1}, [%2];"
                 : "=r"(r0), "=r"(r1) : "r"(addr));
}
__device__ __forceinline__ void mma_bf16(float* c, const uint32_t* a, const uint32_t* b) {
    asm volatile(
        "mma.sync.aligned.m16n8k16.row.col.f32.bf16.bf16.f32 "
        "{%0,%1,%2,%3}, {%4,%5,%6,%7}, {%8,%9}, {%0,%1,%2,%3};"
        : "+f"(c[0]), "+f"(c[1]), "+f"(c[2]), "+f"(c[3])
        : "r"(a[0]), "r"(a[1]), "r"(a[2]), "r"(a[3]), "r"(b[0]), "r"(b[1]));
}
__device__ __forceinline__ void cp_async16(uint32_t saddr, const void* g) {
    asm volatile("cp.async.cg.shared.global [%0], [%1], 16;" :: "r"(saddr), "l"(g));
}
#define CP_COMMIT() asm volatile("cp.async.commit_group;" ::: "memory")
#define CP_WAIT0()  asm volatile("cp.async.wait_group 0;" ::: "memory")
#define CP_WAIT1()  asm volatile("cp.async.wait_group 1;" ::: "memory")

__device__ __forceinline__ uint32_t pk2(__nv_bfloat16 a, __nv_bfloat16 b) {
    __nv_bfloat162 t = __halves2bfloat162(a, b);   // a -> low half
    return *(uint32_t*)&t;
}

// ---------------- conversion kernels ----------------
__global__ __launch_bounds__(256) void split_kernel(
    const float* __restrict__ x, __nv_bfloat16* __restrict__ h,
    __nv_bfloat16* __restrict__ l, int n4)
{
    int i = blockIdx.x * blockDim.x + threadIdx.x;
    if (i >= n4) return;
    float4 v = ((const float4*)x)[i];
    __nv_bfloat16 h0 = __float2bfloat16(v.x);
    __nv_bfloat16 h1 = __float2bfloat16(v.y);
    __nv_bfloat16 h2 = __float2bfloat16(v.z);
    __nv_bfloat16 h3 = __float2bfloat16(v.w);
    __nv_bfloat16 l0 = __float2bfloat16(v.x - __bfloat162float(h0));
    __nv_bfloat16 l1 = __float2bfloat16(v.y - __bfloat162float(h1));
    __nv_bfloat16 l2 = __float2bfloat16(v.z - __bfloat162float(h2));
    __nv_bfloat16 l3 = __float2bfloat16(v.w - __bfloat162float(h3));
    ((__nv_bfloat162*)h)[2 * i]     = __halves2bfloat162(h0, h1);
    ((__nv_bfloat162*)h)[2 * i + 1] = __halves2bfloat162(h2, h3);
    ((__nv_bfloat162*)l)[2 * i]     = __halves2bfloat162(l0, l1);
    ((__nv_bfloat162*)l)[2 * i + 1] = __halves2bfloat162(l2, l3);
}

// W[K][N] (row-major) -> Th[N][K], Tl[N][K] split bf16
__global__ __launch_bounds__(256) void tsplit_kernel(
    const float* __restrict__ W, __nv_bfloat16* __restrict__ Th,
    __nv_bfloat16* __restrict__ Tl)
{
    __shared__ float t[32][33];
    int tx = threadIdx.x, ty = threadIdx.y;
    int bx = blockIdx.x * 32;   // N
    int by = blockIdx.y * 32;   // K
#pragma unroll
    for (int j = 0; j < 32; j += 8)
        t[ty + j][tx] = W[(size_t)(by + ty + j) * HID + bx + tx];
    __syncthreads();
#pragma unroll
    for (int j = 0; j < 32; j += 8) {
        float v = t[tx][ty + j];
        __nv_bfloat16 hb = __float2bfloat16(v);
        float lo = v - __bfloat162float(hb);
        size_t o = (size_t)(bx + ty + j) * HID + by + tx;
        Th[o] = hb;
        Tl[o] = __float2bfloat16(lo);
    }
}

// ---------------- HMMA bf16-split GEMM, 2-stage cp.async ----------------
// C = alpha * (Ah+Al)[M,K] @ (Bh+Bl)^T  (Bt stored [N][K] K-major)
// CTA 128x128, BK=32, 8 warps 2x4, warp tile 64x32.
#define BK 32
#define SSTRIDE 40                         // elems per smem row (80 B)
#define TILE_ELEMS (128 * SSTRIDE)
#define TILE_BYTES (TILE_ELEMS * 2)        // 10240
#define STAGE_BYTES (4 * TILE_BYTES)       // 40960
#define GEMM_SMEM  (2 * STAGE_BYTES)       // 81920

__global__ __launch_bounds__(256) void gemm_mma(
    const __nv_bfloat16* __restrict__ Ah, const __nv_bfloat16* __restrict__ Al,
    const __nv_bfloat16* __restrict__ Bth, const __nv_bfloat16* __restrict__ Btl,
    float* __restrict__ Cf, __nv_bfloat16* __restrict__ Ch, __nv_bfloat16* __restrict__ Cl,
    int M, int N, int K, float alpha, int split_out)
{
    extern __shared__ char dsm[];
    const uint32_t sb = smem_u32(dsm);
    const int tid = threadIdx.x;
    const int wid = tid >> 5;
    const int lid = tid & 31;
    const int row0 = blockIdx.y * 128;
    const int col0 = blockIdx.x * 128;

    const int lr = tid >> 1;
    const int lhalf = (tid & 1) * 16;
    const __nv_bfloat16* gp0 = Ah  + (size_t)(row0 + lr) * K + lhalf;
    const __nv_bfloat16* gp1 = Al  + (size_t)(row0 + lr) * K + lhalf;
    const __nv_bfloat16* gp2 = Bth + (size_t)(col0 + lr) * K + lhalf;
    const __nv_bfloat16* gp3 = Btl + (size_t)(col0 + lr) * K + lhalf;
    const uint32_t soffB = (uint32_t)(lr * SSTRIDE + lhalf) * 2;

    const int warpM = (wid >> 2) * 64;
    const int warpN = (wid & 3) * 32;
    const int aRow = warpM + (lid & 15);
    const int aCol = (lid >> 4) * 8;
    const int bRow = warpN + (lid & 7);
    const int bCol = ((lid >> 3) & 1) * 8;

    float acc[4][4][4];
#pragma unroll
    for (int i = 0; i < 4; i++)
#pragma unroll
        for (int j = 0; j < 4; j++)
#pragma unroll
            for (int k = 0; k < 4; k++) acc[i][j][k] = 0.f;

    auto prefetch = [&](int c, int st) {
        uint32_t base = sb + st * STAGE_BYTES + soffB;
        const __nv_bfloat16* g0 = gp0 + c * BK;
        const __nv_bfloat16* g1 = gp1 + c * BK;
        const __nv_bfloat16* g2 = gp2 + c * BK;
        const __nv_bfloat16* g3 = gp3 + c * BK;
        cp_async16(base,                  g0); cp_async16(base + 16,                  g0 + 8);
        cp_async16(base + TILE_BYTES,     g1); cp_async16(base + TILE_BYTES + 16,     g1 + 8);
        cp_async16(base + 2 * TILE_BYTES, g2); cp_async16(base + 2 * TILE_BYTES + 16, g2 + 8);
        cp_async16(base + 3 * TILE_BYTES, g3); cp_async16(base + 3 * TILE_BYTES + 16, g3 + 8);
    };

    prefetch(0, 0);
    CP_COMMIT();

    const int nch = K / BK;
    for (int c = 0; c < nch; c++) {
        if (c + 1 < nch) {
            prefetch(c + 1, (c + 1) & 1);
            CP_COMMIT();
            CP_WAIT1();
        } else {
            CP_WAIT0();
        }
        __syncthreads();

        const uint32_t st  = sb + (c & 1) * STAGE_BYTES;
        const uint32_t sAh = st;
        const uint32_t sAl = st + TILE_BYTES;
        const uint32_t sBh = st + 2 * TILE_BYTES;
        const uint32_t sBl = st + 3 * TILE_BYTES;

#pragma unroll
        for (int ks = 0; ks < 2; ks++) {
            uint32_t bh[4][2], bl[4][2];
            const uint32_t bOff = (uint32_t)(bRow * SSTRIDE + ks * 16 + bCol) * 2;
#pragma unroll
            for (int nt = 0; nt < 4; nt++) {
                ldsm_x2(bh[nt][0], bh[nt][1], sBh + bOff + nt * 8 * SSTRIDE * 2);
                ldsm_x2(bl[nt][0], bl[nt][1], sBl + bOff + nt * 8 * SSTRIDE * 2);
            }
            const uint32_t aOff = (uint32_t)(aRow * SSTRIDE + ks * 16 + aCol) * 2;
#pragma unroll
            for (int mt = 0; mt < 4; mt++) {
                uint32_t ah[4], al[4];
                ldsm_x4(ah[0], ah[1], ah[2], ah[3], sAh + aOff + mt * 16 * SSTRIDE * 2);
                ldsm_x4(al[0], al[1], al[2], al[3], sAl + aOff + mt * 16 * SSTRIDE * 2);
#pragma unroll
                for (int nt = 0; nt < 4; nt++) {
                    mma_bf16(acc[mt][nt], ah, bh[nt]);
                    mma_bf16(acc[mt][nt], ah, bl[nt]);
                    mma_bf16(acc[mt][nt], al, bh[nt]);
                }
            }
        }
        __syncthreads();
    }

    // ---- epilogue ----
    const int qrow = lid >> 2;
    const int qcol = (lid & 3) * 2;
#pragma unroll
    for (int mt = 0; mt < 4; mt++) {
        const int r0g = row0 + warpM + mt * 16 + qrow;
#pragma unroll
        for (int nt = 0; nt < 4; nt++) {
            const int cg = col0 + warpN + nt * 8 + qcol;
            float v0 = alpha * acc[mt][nt][0];
            float v1 = alpha * acc[mt][nt][1];
            float v2 = alpha * acc[mt][nt][2];
            float v3 = alpha * acc[mt][nt][3];
            if (split_out) {
                __nv_bfloat16 h0 = __float2bfloat16(v0), h1 = __float2bfloat16(v1);
                __nv_bfloat16 h2 = __float2bfloat16(v2), h3 = __float2bfloat16(v3);
                uint32_t hi0 = pk2(h0, h1), hi1 = pk2(h2, h3);
                uint32_t lo0 = pk2(__float2bfloat16(v0 - __bfloat162float(h0)),
                                   __float2bfloat16(v1 - __bfloat162float(h1)));
                uint32_t lo1 = pk2(__float2bfloat16(v2 - __bfloat162float(h2)),
                                   __float2bfloat16(v3 - __bfloat162float(h3)));
                *(uint32_t*)&Ch[(size_t)r0g * N + cg]       = hi0;
                *(uint32_t*)&Cl[(size_t)r0g * N + cg]       = lo0;
                *(uint32_t*)&Ch[(size_t)(r0g + 8) * N + cg] = hi1;
                *(uint32_t*)&Cl[(size_t)(r0g + 8) * N + cg] = lo1;
            } else {
                float2 a0 = {v0, v1}, a1 = {v2, v3};
                *(float2*)&Cf[(size_t)r0g * N + cg]       = a0;
                *(float2*)&Cf[(size_t)(r0g + 8) * N + cg] = a1;
            }
        }
    }
}

// ---------------- mma.sync flash attention ----------------
// CTA = (q-block of 64, head), 4 warps, warp = 16 q-rows.
// Q hi/lo in regs; K/V hi/lo tiles in smem per k-tile.
#define AS 136                                  // smem row stride (elems)
#define ATTN_SMEM (4 * 64 * AS * 2)             // 69632 B

__global__ __launch_bounds__(128) void attn_mma(
    const __nv_bfloat16* __restrict__ Qh, const __nv_bfloat16* __restrict__ Ql,
    const __nv_bfloat16* __restrict__ Kh, const __nv_bfloat16* __restrict__ Kl,
    const __nv_bfloat16* __restrict__ Vh, const __nv_bfloat16* __restrict__ Vl,
    __nv_bfloat16* __restrict__ Oh, __nv_bfloat16* __restrict__ Ol)
{
    extern __shared__ char dsm[];
    __nv_bfloat16* sKh = (__nv_bfloat16*)dsm;
    __nv_bfloat16* sKl = sKh + 64 * AS;
    __nv_bfloat16* sVh = sKl + 64 * AS;
    __nv_bfloat16* sVl = sVh + 64 * AS;
    const uint32_t uKh = smem_u32(sKh), uKl = smem_u32(sKl);
    const uint32_t uVh = smem_u32(sVh), uVl = smem_u32(sVl);

    const int tid = threadIdx.x;
    const int wid = tid >> 5;
    const int lid = tid & 31;
    const int qb = blockIdx.x;
    const int q0 = qb * 64;
    const int h  = blockIdx.y;
    const size_t hoff = (size_t)h * HDIM;

    const int lr = tid >> 1;               // 0..63 (2 threads per row)
    const int lhalf = (tid & 1) * 64;      // elem offset

    // ---- stage Q into sKh/sKl, ldmatrix to regs ----
    {
        const __nv_bfloat16* gqh = Qh + (size_t)(q0 + lr) * HID + hoff + lhalf;
        const __nv_bfloat16* gql = Ql + (size_t)(q0 + lr) * HID + hoff + lhalf;
#pragma unroll
        for (int i = 0; i < 8; i++) {
            *(uint4*)&sKh[lr * AS + lhalf + i * 8] = *(const uint4*)(gqh + i * 8);
            *(uint4*)&sKl[lr * AS + lhalf + i * 8] = *(const uint4*)(gql + i * 8);
        }
    }
    __syncthreads();
    uint32_t qfh[8][4], qfl[8][4];
    {
        const int aRow = wid * 16 + (lid & 15);
        const int aCol = (lid >> 4) * 8;
#pragma unroll
        for (int kt = 0; kt < 8; kt++) {
            uint32_t ao = (uint32_t)(aRow * AS + kt * 16 + aCol) * 2;
            ldsm_x4(qfh[kt][0], qfh[kt][1], qfh[kt][2], qfh[kt][3], uKh + ao);
            ldsm_x4(qfl[kt][0], qfl[kt][1], qfl[kt][2], qfl[kt][3], uKl + ao);
        }
    }
    __syncthreads();

    float oAcc[16][4];
#pragma unroll
    for (int i = 0; i < 16; i++)
#pragma unroll
        for (int j = 0; j < 4; j++) oAcc[i][j] = 0.f;
    float mrow[2] = {-1e30f, -1e30f};
    float lsum[2] = {0.f, 0.f};

    const int row0g = q0 + wid * 16 + (lid >> 2);
    const int row1g = row0g + 8;

    for (int t = 0; t < SEQ / 64; t++) {
        bool include = (qb == 0) || (t == 0) || (t >= qb - 4 && t <= qb + 4);
        if (!include) continue;
        const int k0 = t * 64;

        // ---- load K/V hi/lo tiles ----
        {
            const size_t gb = (size_t)(k0 + lr) * HID + hoff + lhalf;
#pragma unroll
            for (int i = 0; i < 8; i++) {
                *(uint4*)&sKh[lr * AS + lhalf + i * 8] = *(const uint4*)(Kh + gb + i * 8);
                *(uint4*)&sKl[lr * AS + lhalf + i * 8] = *(const uint4*)(Kl + gb + i * 8);
                *(uint4*)&sVh[lr * AS + lhalf + i * 8] = *(const uint4*)(Vh + gb + i * 8);
                *(uint4*)&sVl[lr * AS + lhalf + i * 8] = *(const uint4*)(Vl + gb + i * 8);
            }
        }
        __syncthreads();

        // ---- S = Q K^T (hi/lo split, 3 MMAs) ----
        float p[8][4];
#pragma unroll
        for (int i = 0; i < 8; i++)
#pragma unroll
            for (int j = 0; j < 4; j++) p[i][j] = 0.f;

#pragma unroll
        for (int kt = 0; kt < 8; kt++) {
            const uint32_t bOff = (uint32_t)((lid & 7) * AS + kt * 16 + ((lid >> 3) & 1) * 8) * 2;
#pragma unroll
            for (int nt = 0; nt < 8; nt++) {
                uint32_t kbh[2], kbl[2];
                uint32_t o = bOff + nt * 8 * AS * 2;
                ldsm_x2(kbh[0], kbh[1], uKh + o);
                ldsm_x2(kbl[0], kbl[1], uKl + o);
                mma_bf16(p[nt], qfh[kt], kbh);
                mma_bf16(p[nt], qfh[kt], kbl);
                mma_bf16(p[nt], qfl[kt], kbh);
            }
        }

        // ---- mask (edge tiles only) ----
        bool fullTile = ((t - qb <= 3) && (qb - t <= 3)) || (t == 0 && qb <= 3);
        if (!fullTile) {
            const int cb = k0 + 2 * (lid & 3);
#pragma unroll
            for (int nt = 0; nt < 8; nt++) {
                int kg0 = cb + nt * 8, kg1 = kg0 + 1;
                if (!((row0g < NGLOB) | (kg0 < NGLOB) | (abs(row0g - kg0) < HALFWIN))) p[nt][0] = -1e30f;
                if (!((row0g < NGLOB) | (kg1 < NGLOB) | (abs(row0g - kg1) < HALFWIN))) p[nt][1] = -1e30f;
                if (!((row1g < NGLOB) | (kg0 < NGLOB) | (abs(row1g - kg0) < HALFWIN))) p[nt][2] = -1e30f;
                if (!((row1g < NGLOB) | (kg1 < NGLOB) | (abs(row1g - kg1) < HALFWIN))) p[nt][3] = -1e30f;
            }
        }

        // ---- online softmax (row state per thread, quad-reduced) ----
        float tm0 = -1e30f, tm1 = -1e30f;
#pragma unroll
        for (int nt = 0; nt < 8; nt++) {
            tm0 = fmaxf(tm0, fmaxf(p[nt][0], p[nt][1]));
            tm1 = fmaxf(tm1, fmaxf(p[nt][2], p[nt][3]));
        }
        tm0 = fmaxf(tm0, __shfl_xor_sync(0xffffffffu, tm0, 1));
        tm0 = fmaxf(tm0, __shfl_xor_sync(0xffffffffu, tm0, 2));
        tm1 = fmaxf(tm1, __shfl_xor_sync(0xffffffffu, tm1, 1));
        tm1 = fmaxf(tm1, __shfl_xor_sync(0xffffffffu, tm1, 2));

        float m0 = fmaxf(mrow[0], tm0);
        float m1 = fmaxf(mrow[1], tm1);
        float f0 = __expf(mrow[0] - m0);
        float f1 = __expf(mrow[1] - m1);
        float rs0 = 0.f, rs1 = 0.f;
#pragma unroll
        for (int nt = 0; nt < 8; nt++) {
            p[nt][0] = __expf(p[nt][0] - m0);
            p[nt][1] = __expf(p[nt][1] - m0);
            p[nt][2] = __expf(p[nt][2] - m1);
            p[nt][3] = __expf(p[nt][3] - m1);
            rs0 += p[nt][0] + p[nt][1];
            rs1 += p[nt][2] + p[nt][3];
        }
        rs0 += __shfl_xor_sync(0xffffffffu, rs0, 1);
        rs0 += __shfl_xor_sync(0xffffffffu, rs0, 2);
        rs1 += __shfl_xor_sync(0xffffffffu, rs1, 1);
        rs1 += __shfl_xor_sync(0xffffffffu, rs1, 2);
        lsum[0] = lsum[0] * f0 + rs0;
        lsum[1] = lsum[1] * f1 + rs1;
        mrow[0] = m0;
        mrow[1] = m1;
#pragma unroll
        for (int nt = 0; nt < 16; nt++) {
            oAcc[nt][0] *= f0;
            oAcc[nt][1] *= f0;
            oAcc[nt][2] *= f1;
            oAcc[nt][3] *= f1;
        }

        // ---- O += P V (P hi/lo split from registers, V via ldmatrix.trans) ----
#pragma unroll
        for (int pk = 0; pk < 4; pk++) {
            uint32_t ah[4], al[4];
            {
                const float* pa = p[2 * pk];
                const float* pb = p[2 * pk + 1];
                __nv_bfloat16 ha0 = __float2bfloat16(pa[0]), ha1 = __float2bfloat16(pa[1]);
                __nv_bfloat16 ha2 = __float2bfloat16(pa[2]), ha3 = __float2bfloat16(pa[3]);
                __nv_bfloat16 hb0 = __float2bfloat16(pb[0]), hb1 = __float2bfloat16(pb[1]);
                __nv_bfloat16 hb2 = __float2bfloat16(pb[2]), hb3 = __float2bfloat16(pb[3]);
                ah[0] = pk2(ha0, ha1);
                ah[1] = pk2(ha2, ha3);
                ah[2] = pk2(hb0, hb1);
                ah[3] = pk2(hb2, hb3);
                al[0] = pk2(__float2bfloat16(pa[0] - __bfloat162float(ha0)),
                            __float2bfloat16(pa[1] - __bfloat162float(ha1)));
                al[1] = pk2(__float2bfloat16(pa[2] - __bfloat162float(ha2)),
                            __float2bfloat16(pa[3] - __bfloat162float(ha3)));
                al[2] = pk2(__float2bfloat16(pb[0] - __bfloat162float(hb0)),
                            __float2bfloat16(pb[1] - __bfloat162float(hb1)));
                al[3] = pk2(__float2bfloat16(pb[2] - __bfloat162float(hb2)),
                            __float2bfloat16(pb[3] - __bfloat162float(hb3)));
            }
            const uint32_t vRow = (uint32_t)((pk * 16 + (lid & 15)) * AS) * 2;
#pragma unroll
            for (int nt = 0; nt < 16; nt++) {
                uint32_t bh[2], bl[2];
                ldsm_x2t(bh[0], bh[1], uVh + vRow + nt * 16);
                ldsm_x2t(bl[0], bl[1], uVl + vRow + nt * 16);
                mma_bf16(oAcc[nt], ah, bh);
                mma_bf16(oAcc[nt], ah, bl);
                mma_bf16(oAcc[nt], al, bh);
            }
        }
        __syncthreads();   // protect K/V smem before next tile's loads
    }

    // ---- epilogue: normalize, split to bf16 hi/lo, store ----
    const float inv0 = 1.f / lsum[0];
    const float inv1 = 1.f / lsum[1];
    const int col = (lid & 3) * 2;
#pragma unroll
    for (int nt = 0; nt < 16; nt++) {
        float v0 = oAcc[nt][0] * inv0;
        float v1 = oAcc[nt][1] * inv0;
        float v2 = oAcc[nt][2] * inv1;
        float v3 = oAcc[nt][3] * inv1;
        __nv_bfloat16 h0 = __float2bfloat16(v0), h1 = __float2bfloat16(v1);
        __nv_bfloat16 h2 = __float2bfloat16(v2), h3 = __float2bfloat16(v3);
        size_t o0 = (size_t)row0g * HID + hoff + nt * 8 + col;
        size_t o1 = (size_t)row1g * HID + hoff + nt * 8 + col;
        *(uint32_t*)&Oh[o0] = pk2(h0, h1);
        *(uint32_t*)&Ol[o0] = pk2(__float2bfloat16(v0 - __bfloat162float(h0)),
                                  __float2bfloat16(v1 - __bfloat162float(h1)));
        *(uint32_t*)&Oh[o1] = pk2(h2, h3);
        *(uint32_t*)&Ol[o1] = pk2(__float2bfloat16(v2 - __bfloat162float(h2)),
                                  __float2bfloat16(v3 - __bfloat162float(h3)));
    }
}

// ======================= launch =======================
extern "C" void kernel_launch(void* const* d_in, const int* in_sizes, int n_in,
                              void* d_out, int out_size)
{
    const float* X  = (const float*)d_in[0];
    const float* Wq = (const float*)d_in[1];
    const float* Wk = (const float*)d_in[2];
    const float* Wv = (const float*)d_in[3];
    const float* Wo = (const float*)d_in[4];
    float* out = (float*)d_out;

    __nv_bfloat16 *xh, *xl, *qh, *ql, *kh, *kl, *vh, *vl, *oh, *ol;
    cudaGetSymbolAddress((void**)&xh, g_Xh);
    cudaGetSymbolAddress((void**)&xl, g_Xl);
    cudaGetSymbolAddress((void**)&qh, g_Qh);
    cudaGetSymbolAddress((void**)&ql, g_Ql);
    cudaGetSymbolAddress((void**)&kh, g_Kh);
    cudaGetSymbolAddress((void**)&kl, g_Kl);
    cudaGetSymbolAddress((void**)&vh, g_Vh);
    cudaGetSymbolAddress((void**)&vl, g_Vl);
    cudaGetSymbolAddress((void**)&oh, g_Oh);
    cudaGetSymbolAddress((void**)&ol, g_Ol);
    __nv_bfloat16 *wqh, *wql, *wkh, *wkl, *wvh, *wvl, *woh, *wol;
    cudaGetSymbolAddress((void**)&wqh, g_Wqh);
    cudaGetSymbolAddress((void**)&wql, g_Wql);
    cudaGetSymbolAddress((void**)&wkh, g_Wkh);
    cudaGetSymbolAddress((void**)&wkl, g_Wkl);
    cudaGetSymbolAddress((void**)&wvh, g_Wvh);
    cudaGetSymbolAddress((void**)&wvl, g_Wvl);
    cudaGetSymbolAddress((void**)&woh, g_Woh);
    cudaGetSymbolAddress((void**)&wol, g_Wol);

    cudaFuncSetAttribute(gemm_mma,
                         cudaFuncAttributeMaxDynamicSharedMemorySize, GEMM_SMEM);
    cudaFuncSetAttribute(attn_mma,
                         cudaFuncAttributeMaxDynamicSharedMemorySize, ATTN_SMEM);

    const int n4 = SEQ * HID / 4;
    split_kernel<<<(n4 + 255) / 256, 256>>>(X, xh, xl, n4);
    dim3 tG(HID / 32, HID / 32);
    dim3 tB(32, 8);
    tsplit_kernel<<<tG, tB>>>(Wq, wqh, wql);
    tsplit_kernel<<<tG, tB>>>(Wk, wkh, wkl);
    tsplit_kernel<<<tG, tB>>>(Wv, wvh, wvl);
    tsplit_kernel<<<tG, tB>>>(Wo, woh, wol);

    dim3 gG(HID / 128, SEQ / 128);   // (16, 32)
    gemm_mma<<<gG, 256, GEMM_SMEM>>>(xh, xl, wqh, wql, nullptr, qh, ql,
                                     SEQ, HID, HID, SCALE, 1);
    gemm_mma<<<gG, 256, GEMM_SMEM>>>(xh, xl, wkh, wkl, nullptr, kh, kl,
                                     SEQ, HID, HID, 1.0f, 1);
    gemm_mma<<<gG, 256, GEMM_SMEM>>>(xh, xl, wvh, wvl, nullptr, vh, vl,
                                     SEQ, HID, HID, 1.0f, 1);

    attn_mma<<<dim3(SEQ / 64, NHEADS), 128, ATTN_SMEM>>>(qh, ql, kh, kl, vh, vl, oh, ol);

    gemm_mma<<<gG, 256, GEMM_SMEM>>>(oh, ol, woh, wol, out, nullptr, nullptr,
                                     SEQ, HID, HID, 1.0f, 0);
}